// round 2
// baseline (speedup 1.0000x reference)
#include <cuda_runtime.h>
#include <cuda_bf16.h>
#include <math.h>

// Problem constants (fixed by setup_inputs)
#define BATCH 2
#define NQ 2048
#define NKV 2112
#define CDIM 1024
#define NH 16
#define HD 64
#define NKEEP 2048          // NKV - num_final_k_to_exclude
#define QW 64               // q_w
#define SCALE 0.125f        // 1/sqrt(64)

// Scratch (device globals; allocation is forbidden)
__device__ float g_Qh[BATCH * NH * NQ * HD];      // 16 MB
__device__ float g_Kh[BATCH * NH * NKV * HD];     // 16.5 MB
__device__ float g_Vh[BATCH * NH * NKV * HD];     // 16.5 MB
__device__ float g_AO[BATCH * NQ * CDIM];         // 16 MB
__device__ float g_ct[NQ * 32];
__device__ float g_st[NQ * 32];

// ---------------------------------------------------------------------------
// RoPE cos/sin table: ang[n][p] = (p<16 ? n%64 : n/64) * theta^{-(p%16)/16}
// ---------------------------------------------------------------------------
__global__ void rope_table_kernel(float* __restrict__ ct, float* __restrict__ st) {
    int idx = blockIdx.x * blockDim.x + threadIdx.x;
    if (idx >= NQ * 32) return;
    int n = idx >> 5;
    int p = idx & 31;
    int j = p & 15;
    float coord = (p < 16) ? (float)(n & (QW - 1)) : (float)(n / QW);
    float freq = powf(10000.0f, -(float)j / 16.0f);
    float ang = coord * freq;
    ct[idx] = cosf(ang);
    st[idx] = sinf(ang);
}

// ---------------------------------------------------------------------------
// SGEMM: out = X(M x 1024) @ W(1024 x 1024) + bias, with epilogue modes:
//  mode 0: scatter to head layout [b][h][n][d]   (V)
//  mode 1: head layout + RoPE on all rows        (Q)
//  mode 2: head layout + RoPE when n < NKEEP     (K)
//  mode 3: plain row-major (final projection)
// BM=BN=128, BK=8, 256 threads, 8x8 micro-tile.
// ---------------------------------------------------------------------------
__global__ __launch_bounds__(256)
void sgemm_kernel(const float* __restrict__ A, const float* __restrict__ W,
                  const float* __restrict__ bias, float* __restrict__ out,
                  int Ntok, int mode,
                  const float* __restrict__ ct, const float* __restrict__ st) {
    __shared__ float As[8][128];
    __shared__ float Bs[8][128];

    const int K = 1024, N = 1024;
    int tid = threadIdx.x;
    int tx = tid & 15;          // 0..15  (col group)
    int ty = tid >> 4;          // 0..15  (row group)
    int row0 = blockIdx.y * 128;
    int col0 = blockIdx.x * 128;

    int arow = tid >> 1;              // 0..127
    int acol = (tid & 1) << 2;        // 0 or 4
    int brow = tid >> 5;              // 0..7
    int bcol = (tid & 31) << 2;       // 0..124

    float acc[8][8];
#pragma unroll
    for (int i = 0; i < 8; i++)
#pragma unroll
        for (int j = 0; j < 8; j++) acc[i][j] = 0.0f;

    const float* Aptr = A + (size_t)(row0 + arow) * K + acol;
    const float* Wptr = W + (size_t)brow * N + col0 + bcol;

    for (int k0 = 0; k0 < K; k0 += 8) {
        float4 av = *(const float4*)(Aptr + k0);
        As[acol + 0][arow] = av.x;
        As[acol + 1][arow] = av.y;
        As[acol + 2][arow] = av.z;
        As[acol + 3][arow] = av.w;
        float4 bv = *(const float4*)(Wptr + (size_t)k0 * N);
        *(float4*)&Bs[brow][bcol] = bv;
        __syncthreads();

#pragma unroll
        for (int kk = 0; kk < 8; kk++) {
            float4 a0 = *(const float4*)&As[kk][ty * 8];
            float4 a1 = *(const float4*)&As[kk][ty * 8 + 4];
            float4 b0 = *(const float4*)&Bs[kk][tx * 8];
            float4 b1 = *(const float4*)&Bs[kk][tx * 8 + 4];
            float a[8] = {a0.x, a0.y, a0.z, a0.w, a1.x, a1.y, a1.z, a1.w};
            float b[8] = {b0.x, b0.y, b0.z, b0.w, b1.x, b1.y, b1.z, b1.w};
#pragma unroll
            for (int i = 0; i < 8; i++)
#pragma unroll
                for (int j = 0; j < 8; j++) acc[i][j] = fmaf(a[i], b[j], acc[i][j]);
        }
        __syncthreads();
    }

    int gc0 = col0 + tx * 8;
    float bvals[8];
#pragma unroll
    for (int j = 0; j < 8; j++) bvals[j] = bias[gc0 + j];

#pragma unroll
    for (int i = 0; i < 8; i++) {
        int gr = row0 + ty * 8 + i;
        float vals[8];
#pragma unroll
        for (int j = 0; j < 8; j++) vals[j] = acc[i][j] + bvals[j];

        if (mode == 3) {
            float* dst = out + (size_t)gr * 1024 + gc0;
            *(float4*)dst = make_float4(vals[0], vals[1], vals[2], vals[3]);
            *(float4*)(dst + 4) = make_float4(vals[4], vals[5], vals[6], vals[7]);
        } else {
            int b = gr / Ntok;
            int n = gr - b * Ntok;
            bool dorope = (mode == 1) || (mode == 2 && n < NKEEP);
            if (dorope) {
#pragma unroll
                for (int j = 0; j < 8; j += 2) {
                    int dd = (gc0 + j) & 63;
                    int p = dd >> 1;
                    float cs = ct[n * 32 + p];
                    float sn = st[n * 32 + p];
                    float e = vals[j], o = vals[j + 1];
                    vals[j]     = e * cs - o * sn;
                    vals[j + 1] = e * sn + o * cs;
                }
            }
            int h = gc0 >> 6;
            int dd0 = gc0 & 63;
            float* dst = out + (((size_t)(b * NH + h) * Ntok + n) * HD + dd0);
            *(float4*)dst = make_float4(vals[0], vals[1], vals[2], vals[3]);
            *(float4*)(dst + 4) = make_float4(vals[4], vals[5], vals[6], vals[7]);
        }
    }
}

// ---------------------------------------------------------------------------
// Flash attention: per block one (b,h) pair and 64 query rows.
// Br=64, Bc=32, 256 threads: thread t -> row r = t/4, segment seg = t%4
//  (8 score columns per thread, 16 output dims per thread).
// ---------------------------------------------------------------------------
__global__ __launch_bounds__(256)
void flash_attn_kernel(const float* __restrict__ Qh, const float* __restrict__ Kh,
                       const float* __restrict__ Vh, float* __restrict__ Out) {
    __shared__ float Qs[64][64];      // 16 KB
    __shared__ float Ks[32][68];      // 8.5 KB (pad keeps 16B alignment, avoids conflicts)
    __shared__ float Vs[32][68];      // 8.5 KB
    __shared__ float Ss[64][33];      // 8.25 KB

    int bh = blockIdx.y;              // 0..31
    int qt = blockIdx.x;              // 0..31
    int tid = threadIdx.x;
    int r = tid >> 2;                 // 0..63
    int seg = tid & 3;                // 0..3

    const float* Qb = Qh + (size_t)bh * NQ * HD + (size_t)qt * 64 * HD;
    const float* Kb = Kh + (size_t)bh * NKV * HD;
    const float* Vb = Vh + (size_t)bh * NKV * HD;

    // Load + scale Q tile (4096 floats)
    const float4* Qsrc = (const float4*)Qb;
    for (int i = tid; i < 1024; i += 256) {
        float4 q = Qsrc[i];
        q.x *= SCALE; q.y *= SCALE; q.z *= SCALE; q.w *= SCALE;
        int rr = i >> 4;
        int cc = (i & 15) << 2;
        *(float4*)&Qs[rr][cc] = q;
    }
    __syncthreads();

    float m = -INFINITY, l = 0.0f;
    float o[16];
#pragma unroll
    for (int i = 0; i < 16; i++) o[i] = 0.0f;

    for (int kt = 0; kt < NKV / 32; kt++) {
        const float4* Ksrc = (const float4*)(Kb + (size_t)kt * 32 * HD);
        const float4* Vsrc = (const float4*)(Vb + (size_t)kt * 32 * HD);
#pragma unroll
        for (int it = 0; it < 2; it++) {
            int i = tid + it * 256;
            int rr = i >> 4;
            int cc = (i & 15) << 2;
            *(float4*)&Ks[rr][cc] = Ksrc[i];
            *(float4*)&Vs[rr][cc] = Vsrc[i];
        }
        __syncthreads();

        // Scores for 8 key columns
        float s[8];
#pragma unroll
        for (int j = 0; j < 8; j++) s[j] = 0.0f;
#pragma unroll 8
        for (int kk = 0; kk < 64; kk += 4) {
            float4 qv = *(const float4*)&Qs[r][kk];
#pragma unroll
            for (int j = 0; j < 8; j++) {
                int jc = (seg << 3) + j;
                float4 kv = *(const float4*)&Ks[jc][kk];
                s[j] += qv.x * kv.x + qv.y * kv.y + qv.z * kv.z + qv.w * kv.w;
            }
        }

        // Online softmax update (quad = 4 threads of the same row)
        float mt = s[0];
#pragma unroll
        for (int j = 1; j < 8; j++) mt = fmaxf(mt, s[j]);
        mt = fmaxf(mt, __shfl_xor_sync(0xffffffffu, mt, 1));
        mt = fmaxf(mt, __shfl_xor_sync(0xffffffffu, mt, 2));
        float mnew = fmaxf(m, mt);
        float alpha = __expf(m - mnew);
        float lsum = 0.0f;
#pragma unroll
        for (int j = 0; j < 8; j++) {
            float p = __expf(s[j] - mnew);
            s[j] = p;
            lsum += p;
        }
        lsum += __shfl_xor_sync(0xffffffffu, lsum, 1);
        lsum += __shfl_xor_sync(0xffffffffu, lsum, 2);
        l = l * alpha + lsum;
        m = mnew;
#pragma unroll
        for (int i = 0; i < 16; i++) o[i] *= alpha;

#pragma unroll
        for (int j = 0; j < 8; j++) Ss[r][(seg << 3) + j] = s[j];
        __syncthreads();

        // O += P @ V  (this thread: dims seg*16 .. seg*16+15)
        int dc = seg << 4;
#pragma unroll 8
        for (int j = 0; j < 32; j++) {
            float p = Ss[r][j];
            float4 v0 = *(const float4*)&Vs[j][dc];
            float4 v1 = *(const float4*)&Vs[j][dc + 4];
            float4 v2 = *(const float4*)&Vs[j][dc + 8];
            float4 v3 = *(const float4*)&Vs[j][dc + 12];
            o[0]  = fmaf(p, v0.x, o[0]);  o[1]  = fmaf(p, v0.y, o[1]);
            o[2]  = fmaf(p, v0.z, o[2]);  o[3]  = fmaf(p, v0.w, o[3]);
            o[4]  = fmaf(p, v1.x, o[4]);  o[5]  = fmaf(p, v1.y, o[5]);
            o[6]  = fmaf(p, v1.z, o[6]);  o[7]  = fmaf(p, v1.w, o[7]);
            o[8]  = fmaf(p, v2.x, o[8]);  o[9]  = fmaf(p, v2.y, o[9]);
            o[10] = fmaf(p, v2.z, o[10]); o[11] = fmaf(p, v2.w, o[11]);
            o[12] = fmaf(p, v3.x, o[12]); o[13] = fmaf(p, v3.y, o[13]);
            o[14] = fmaf(p, v3.z, o[14]); o[15] = fmaf(p, v3.w, o[15]);
        }
        __syncthreads();
    }

    float inv = 1.0f / l;
    int b = bh >> 4;
    int h = bh & 15;
    size_t base = ((size_t)(b * NQ + qt * 64 + r)) * CDIM + h * HD + (seg << 4);
#pragma unroll
    for (int g = 0; g < 4; g++) {
        float4 t = make_float4(o[4 * g] * inv, o[4 * g + 1] * inv,
                               o[4 * g + 2] * inv, o[4 * g + 3] * inv);
        *(float4*)&Out[base + 4 * g] = t;
    }
}

// ---------------------------------------------------------------------------
extern "C" void kernel_launch(void* const* d_in, const int* in_sizes, int n_in,
                              void* d_out, int out_size) {
    const float* q  = (const float*)d_in[0];
    const float* k  = (const float*)d_in[1];
    const float* v  = (const float*)d_in[2];
    const float* Wq = (const float*)d_in[3];
    const float* bq = (const float*)d_in[4];
    const float* Wk = (const float*)d_in[5];
    const float* bk = (const float*)d_in[6];
    const float* Wv = (const float*)d_in[7];
    const float* bv = (const float*)d_in[8];
    const float* Wo = (const float*)d_in[9];
    const float* bo = (const float*)d_in[10];
    float* out = (float*)d_out;

    float *pQ, *pK, *pV, *pAO, *pc, *ps;
    cudaGetSymbolAddress((void**)&pQ,  g_Qh);
    cudaGetSymbolAddress((void**)&pK,  g_Kh);
    cudaGetSymbolAddress((void**)&pV,  g_Vh);
    cudaGetSymbolAddress((void**)&pAO, g_AO);
    cudaGetSymbolAddress((void**)&pc,  g_ct);
    cudaGetSymbolAddress((void**)&ps,  g_st);

    rope_table_kernel<<<(NQ * 32 + 255) / 256, 256>>>(pc, ps);

    // Projections (fused bias + RoPE + head-layout scatter)
    sgemm_kernel<<<dim3(8, (BATCH * NQ) / 128),  256>>>(q, Wq, bq, pQ, NQ,  1, pc, ps);
    sgemm_kernel<<<dim3(8, (BATCH * NKV) / 128), 256>>>(k, Wk, bk, pK, NKV, 2, pc, ps);
    sgemm_kernel<<<dim3(8, (BATCH * NKV) / 128), 256>>>(v, Wv, bv, pV, NKV, 0, pc, ps);

    // Attention
    flash_attn_kernel<<<dim3(NQ / 64, BATCH * NH), 256>>>(pQ, pK, pV, pAO);

    // Output projection straight into d_out
    sgemm_kernel<<<dim3(8, (BATCH * NQ) / 128), 256>>>(pAO, Wo, bo, out, NQ, 3, pc, ps);
}

// round 5
// speedup vs baseline: 8.4570x; 8.4570x over previous
#include <cuda_runtime.h>
#include <math.h>
#include <stdint.h>

#define BATCH 2
#define NQ 2048
#define NKV 2112
#define CDIM 1024
#define NH 16
#define HD 64
#define NKEEP 2048
#define QW 64
#define SCALE 0.125f

// Scratch (device globals; allocation is forbidden)
__device__ float g_Qh[BATCH * NH * NQ * HD];
__device__ float g_Kh[BATCH * NH * NKV * HD];
__device__ float g_Vh[BATCH * NH * NKV * HD];
__device__ float g_AO[BATCH * NQ * CDIM];
__device__ float g_ct[NQ * 32];
__device__ float g_st[NQ * 32];

// ---------------------------------------------------------------------------
__device__ __forceinline__ float f2tf(float f) {
    uint32_t u;
    asm("cvt.rna.tf32.f32 %0, %1;" : "=r"(u) : "f"(f));
    return __uint_as_float(u);
}

__device__ __forceinline__ void mma8(float c[4], float a0, float a1, float a2, float a3,
                                     float b0, float b1) {
    asm volatile(
        "mma.sync.aligned.m16n8k8.row.col.f32.tf32.tf32.f32 "
        "{%0,%1,%2,%3}, {%4,%5,%6,%7}, {%8,%9}, {%0,%1,%2,%3};\n"
        : "+f"(c[0]), "+f"(c[1]), "+f"(c[2]), "+f"(c[3])
        : "r"(__float_as_uint(a0)), "r"(__float_as_uint(a1)),
          "r"(__float_as_uint(a2)), "r"(__float_as_uint(a3)),
          "r"(__float_as_uint(b0)), "r"(__float_as_uint(b1)));
}

// ---------------------------------------------------------------------------
__global__ void rope_table_kernel(float* __restrict__ ct, float* __restrict__ st) {
    int idx = blockIdx.x * blockDim.x + threadIdx.x;
    if (idx >= NQ * 32) return;
    int n = idx >> 5;
    int p = idx & 31;
    int j = p & 15;
    float coord = (p < 16) ? (float)(n & (QW - 1)) : (float)(n / QW);
    float freq = powf(10000.0f, -(float)j / 16.0f);
    float ang = coord * freq;
    ct[idx] = cosf(ang);
    st[idx] = sinf(ang);
}

// ---------------------------------------------------------------------------
// tf32 tensor-core GEMM: out = X(M x 1024) @ W(1024 x 1024) + bias.
// Block 128x128, BK=32, 256 threads, 8 warps in 4(M) x 2(N), warp tile 32x64.
// Epilogue modes: 0 = head scatter (V), 1 = head + RoPE (Q),
//                 2 = head + RoPE if n < NKEEP (K), 3 = row-major (out proj).
// ---------------------------------------------------------------------------
#define AS_S 36
#define BS_S 132

__global__ __launch_bounds__(256)
void gemm_tf32(const float* __restrict__ A, const float* __restrict__ W,
               const float* __restrict__ bias, float* __restrict__ out,
               int Ntok, int mode,
               const float* __restrict__ ct, const float* __restrict__ st) {
    __shared__ float As[128][AS_S];   // [m][k]
    __shared__ float Bs[32][BS_S];    // [k][n]

    int tid = threadIdx.x;
    int lane = tid & 31, wid = tid >> 5;
    int wm = wid >> 1, wn = wid & 1;
    int g = lane >> 2, q4 = lane & 3;
    int row0 = blockIdx.y * 128, col0 = blockIdx.x * 128;

    float acc[2][8][4];
#pragma unroll
    for (int mi = 0; mi < 2; mi++)
#pragma unroll
        for (int ni = 0; ni < 8; ni++)
#pragma unroll
            for (int j = 0; j < 4; j++) acc[mi][ni][j] = 0.0f;

    for (int k0 = 0; k0 < 1024; k0 += 32) {
        // stage A tile 128x32
#pragma unroll
        for (int t = 0; t < 4; t++) {
            int idx = tid + t * 256;
            int r = idx >> 3, kg = (idx & 7) << 2;
            float4 v = *(const float4*)(A + (size_t)(row0 + r) * 1024 + k0 + kg);
            float4 w = make_float4(f2tf(v.x), f2tf(v.y), f2tf(v.z), f2tf(v.w));
            *(float4*)&As[r][kg] = w;
        }
        // stage B tile 32x128
#pragma unroll
        for (int t = 0; t < 4; t++) {
            int idx = tid + t * 256;
            int r = idx >> 5, ng = (idx & 31) << 2;
            float4 v = *(const float4*)(W + (size_t)(k0 + r) * 1024 + col0 + ng);
            float4 w = make_float4(f2tf(v.x), f2tf(v.y), f2tf(v.z), f2tf(v.w));
            *(float4*)&Bs[r][ng] = w;
        }
        __syncthreads();

#pragma unroll
        for (int kc = 0; kc < 32; kc += 8) {
            float a[2][4], b[8][2];
#pragma unroll
            for (int mi = 0; mi < 2; mi++) {
                int m = wm * 32 + mi * 16;
                a[mi][0] = As[m + g][kc + q4];
                a[mi][1] = As[m + 8 + g][kc + q4];
                a[mi][2] = As[m + g][kc + 4 + q4];
                a[mi][3] = As[m + 8 + g][kc + 4 + q4];
            }
#pragma unroll
            for (int ni = 0; ni < 8; ni++) {
                int n = wn * 64 + ni * 8;
                b[ni][0] = Bs[kc + q4][n + g];
                b[ni][1] = Bs[kc + 4 + q4][n + g];
            }
#pragma unroll
            for (int mi = 0; mi < 2; mi++)
#pragma unroll
                for (int ni = 0; ni < 8; ni++)
                    mma8(acc[mi][ni], a[mi][0], a[mi][1], a[mi][2], a[mi][3],
                         b[ni][0], b[ni][1]);
        }
        __syncthreads();
    }

    // epilogue
#pragma unroll
    for (int mi = 0; mi < 2; mi++) {
#pragma unroll
        for (int ri = 0; ri < 2; ri++) {
            int gr = row0 + wm * 32 + mi * 16 + ri * 8 + g;
            int b = 0, n = gr;
            if (mode != 3) { b = gr / Ntok; n = gr - b * Ntok; }
            bool dorope = (mode == 1) || (mode == 2 && n < NKEEP);
#pragma unroll
            for (int ni = 0; ni < 8; ni++) {
                int gc = col0 + wn * 64 + ni * 8 + 2 * q4;
                float v0 = acc[mi][ni][ri * 2 + 0] + bias[gc];
                float v1 = acc[mi][ni][ri * 2 + 1] + bias[gc + 1];
                if (mode == 3) {
                    *(float2*)(out + (size_t)gr * 1024 + gc) = make_float2(v0, v1);
                } else {
                    if (dorope) {
                        int p = (gc & 63) >> 1;
                        float cs = ct[n * 32 + p];
                        float sn = st[n * 32 + p];
                        float e = v0, o = v1;
                        v0 = e * cs - o * sn;
                        v1 = e * sn + o * cs;
                    }
                    int h = (gc >> 6) & 15;
                    float* dst = out + (((size_t)(b * NH + h) * Ntok + n) * HD + (gc & 63));
                    *(float2*)dst = make_float2(v0, v1);
                }
            }
        }
    }
}

// ---------------------------------------------------------------------------
// tf32 flash attention: block = one (b,h), 128 q rows; 8 warps x 16 rows.
// Bc = 64 keys/iter; S and PV on tensor cores; P via warp-private smem slab.
// ---------------------------------------------------------------------------
#define QS_S 68
#define KS_S 68
#define VS_S 72
#define PS_S 68
#define FLASH_SMEM ((128 * QS_S + 64 * KS_S + 64 * VS_S + 128 * PS_S) * 4)

__global__ __launch_bounds__(256)
void flash_tf32(const float* __restrict__ Qh, const float* __restrict__ Kh,
                const float* __restrict__ Vh, float* __restrict__ Out) {
    extern __shared__ float sm[];
    float* Qs = sm;                        // [128][68]
    float* Ks = Qs + 128 * QS_S;           // [64][68]
    float* Vs = Ks + 64 * KS_S;            // [64][72]
    float* Ps = Vs + 64 * VS_S;            // [128][68]

    int tid = threadIdx.x, lane = tid & 31, wid = tid >> 5;
    int g = lane >> 2, q4 = lane & 3;
    int bh = blockIdx.y, qt = blockIdx.x;
    int r0 = wid * 16;

    const float* Qb = Qh + ((size_t)bh * NQ + qt * 128) * HD;
    const float* Kb = Kh + (size_t)bh * NKV * HD;
    const float* Vb = Vh + (size_t)bh * NKV * HD;

    // stage Q (scaled, tf32)
#pragma unroll
    for (int t = 0; t < 8; t++) {
        int idx = tid + t * 256;
        int r = idx >> 4, dg = (idx & 15) << 2;
        float4 v = *(const float4*)(Qb + r * 64 + dg);
        float4 w = make_float4(f2tf(v.x * SCALE), f2tf(v.y * SCALE),
                               f2tf(v.z * SCALE), f2tf(v.w * SCALE));
        *(float4*)&Qs[r * QS_S + dg] = w;
    }

    float m0 = -INFINITY, m1 = -INFINITY, l0 = 0.0f, l1 = 0.0f;
    float o[8][4];
#pragma unroll
    for (int ni = 0; ni < 8; ni++)
#pragma unroll
        for (int j = 0; j < 4; j++) o[ni][j] = 0.0f;

    for (int kt = 0; kt < NKV / 64; kt++) {
        __syncthreads();
        const float* Ksrc = Kb + (size_t)kt * 64 * 64;
        const float* Vsrc = Vb + (size_t)kt * 64 * 64;
#pragma unroll
        for (int t = 0; t < 4; t++) {
            int idx = tid + t * 256;
            int r = idx >> 4, dg = (idx & 15) << 2;
            float4 kv = *(const float4*)(Ksrc + r * 64 + dg);
            *(float4*)&Ks[r * KS_S + dg] =
                make_float4(f2tf(kv.x), f2tf(kv.y), f2tf(kv.z), f2tf(kv.w));
            float4 vv = *(const float4*)(Vsrc + r * 64 + dg);
            *(float4*)&Vs[r * VS_S + dg] =
                make_float4(f2tf(vv.x), f2tf(vv.y), f2tf(vv.z), f2tf(vv.w));
        }
        __syncthreads();

        // S = Q @ K^T  (16 x 64 per warp)
        float s[8][4];
#pragma unroll
        for (int ni = 0; ni < 8; ni++)
#pragma unroll
            for (int j = 0; j < 4; j++) s[ni][j] = 0.0f;

#pragma unroll
        for (int kc = 0; kc < 64; kc += 8) {
            float a0 = Qs[(r0 + g) * QS_S + kc + q4];
            float a1 = Qs[(r0 + 8 + g) * QS_S + kc + q4];
            float a2 = Qs[(r0 + g) * QS_S + kc + 4 + q4];
            float a3 = Qs[(r0 + 8 + g) * QS_S + kc + 4 + q4];
#pragma unroll
            for (int ni = 0; ni < 8; ni++) {
                float b0 = Ks[(ni * 8 + g) * KS_S + kc + q4];
                float b1 = Ks[(ni * 8 + g) * KS_S + kc + 4 + q4];
                mma8(s[ni], a0, a1, a2, a3, b0, b1);
            }
        }

        // online softmax (rows r0+g and r0+8+g)
        float mt0 = -INFINITY, mt1 = -INFINITY;
#pragma unroll
        for (int ni = 0; ni < 8; ni++) {
            mt0 = fmaxf(mt0, fmaxf(s[ni][0], s[ni][1]));
            mt1 = fmaxf(mt1, fmaxf(s[ni][2], s[ni][3]));
        }
        mt0 = fmaxf(mt0, __shfl_xor_sync(0xffffffffu, mt0, 1));
        mt0 = fmaxf(mt0, __shfl_xor_sync(0xffffffffu, mt0, 2));
        mt1 = fmaxf(mt1, __shfl_xor_sync(0xffffffffu, mt1, 1));
        mt1 = fmaxf(mt1, __shfl_xor_sync(0xffffffffu, mt1, 2));
        float mn0 = fmaxf(m0, mt0), mn1 = fmaxf(m1, mt1);
        float al0 = __expf(m0 - mn0), al1 = __expf(m1 - mn1);
        m0 = mn0; m1 = mn1;

        float sum0 = 0.0f, sum1 = 0.0f;
#pragma unroll
        for (int ni = 0; ni < 8; ni++) {
            s[ni][0] = __expf(s[ni][0] - mn0);
            s[ni][1] = __expf(s[ni][1] - mn0);
            s[ni][2] = __expf(s[ni][2] - mn1);
            s[ni][3] = __expf(s[ni][3] - mn1);
            sum0 += s[ni][0] + s[ni][1];
            sum1 += s[ni][2] + s[ni][3];
        }
        sum0 += __shfl_xor_sync(0xffffffffu, sum0, 1);
        sum0 += __shfl_xor_sync(0xffffffffu, sum0, 2);
        sum1 += __shfl_xor_sync(0xffffffffu, sum1, 1);
        sum1 += __shfl_xor_sync(0xffffffffu, sum1, 2);
        l0 = l0 * al0 + sum0;
        l1 = l1 * al1 + sum1;
#pragma unroll
        for (int ni = 0; ni < 8; ni++) {
            o[ni][0] *= al0; o[ni][1] *= al0;
            o[ni][2] *= al1; o[ni][3] *= al1;
        }

        // write P (warp-private slab), tf32
#pragma unroll
        for (int ni = 0; ni < 8; ni++) {
            int c = ni * 8 + 2 * q4;
            *(float2*)&Ps[(r0 + g) * PS_S + c] =
                make_float2(f2tf(s[ni][0]), f2tf(s[ni][1]));
            *(float2*)&Ps[(r0 + 8 + g) * PS_S + c] =
                make_float2(f2tf(s[ni][2]), f2tf(s[ni][3]));
        }
        __syncwarp();

        // O += P @ V
#pragma unroll
        for (int kc = 0; kc < 64; kc += 8) {
            float a0 = Ps[(r0 + g) * PS_S + kc + q4];
            float a1 = Ps[(r0 + 8 + g) * PS_S + kc + q4];
            float a2 = Ps[(r0 + g) * PS_S + kc + 4 + q4];
            float a3 = Ps[(r0 + 8 + g) * PS_S + kc + 4 + q4];
#pragma unroll
            for (int ni = 0; ni < 8; ni++) {
                float b0 = Vs[(kc + q4) * VS_S + ni * 8 + g];
                float b1 = Vs[(kc + 4 + q4) * VS_S + ni * 8 + g];
                mma8(o[ni], a0, a1, a2, a3, b0, b1);
            }
        }
    }

    // epilogue: write to (B, Nq, C) layout
    float inv0 = 1.0f / l0, inv1 = 1.0f / l1;
    int b = bh >> 4, h = bh & 15;
    int nr = qt * 128 + r0 + g;
    size_t base0 = ((size_t)(b * NQ + nr)) * CDIM + h * 64;
    size_t base1 = base0 + (size_t)8 * CDIM;
#pragma unroll
    for (int ni = 0; ni < 8; ni++) {
        int c = ni * 8 + 2 * q4;
        *(float2*)(Out + base0 + c) = make_float2(o[ni][0] * inv0, o[ni][1] * inv0);
        *(float2*)(Out + base1 + c) = make_float2(o[ni][2] * inv1, o[ni][3] * inv1);
    }
}

// ---------------------------------------------------------------------------
extern "C" void kernel_launch(void* const* d_in, const int* in_sizes, int n_in,
                              void* d_out, int out_size) {
    const float* q  = (const float*)d_in[0];
    const float* k  = (const float*)d_in[1];
    const float* v  = (const float*)d_in[2];
    const float* Wq = (const float*)d_in[3];
    const float* bq = (const float*)d_in[4];
    const float* Wk = (const float*)d_in[5];
    const float* bk = (const float*)d_in[6];
    const float* Wv = (const float*)d_in[7];
    const float* bv = (const float*)d_in[8];
    const float* Wo = (const float*)d_in[9];
    const float* bo = (const float*)d_in[10];
    float* out = (float*)d_out;

    float *pQ, *pK, *pV, *pAO, *pc, *ps;
    cudaGetSymbolAddress((void**)&pQ,  g_Qh);
    cudaGetSymbolAddress((void**)&pK,  g_Kh);
    cudaGetSymbolAddress((void**)&pV,  g_Vh);
    cudaGetSymbolAddress((void**)&pAO, g_AO);
    cudaGetSymbolAddress((void**)&pc,  g_ct);
    cudaGetSymbolAddress((void**)&ps,  g_st);

    cudaFuncSetAttribute(flash_tf32, cudaFuncAttributeMaxDynamicSharedMemorySize,
                         FLASH_SMEM);

    rope_table_kernel<<<(NQ * 32 + 255) / 256, 256>>>(pc, ps);

    gemm_tf32<<<dim3(8, (BATCH * NQ)  / 128), 256>>>(q, Wq, bq, pQ, NQ,  1, pc, ps);
    gemm_tf32<<<dim3(8, (BATCH * NKV) / 128), 256>>>(k, Wk, bk, pK, NKV, 2, pc, ps);
    gemm_tf32<<<dim3(8, (BATCH * NKV) / 128), 256>>>(v, Wv, bv, pV, NKV, 0, pc, ps);

    flash_tf32<<<dim3(NQ / 128, BATCH * NH), 256, FLASH_SMEM>>>(pQ, pK, pV, pAO);

    gemm_tf32<<<dim3(8, (BATCH * NQ) / 128), 256>>>(pAO, Wo, bo, out, NQ, 3, pc, ps);
}

// round 6
// speedup vs baseline: 9.2306x; 1.0915x over previous
#include <cuda_runtime.h>
#include <math.h>
#include <stdint.h>

#define BATCH 2
#define NQ 2048
#define NKV 2112
#define CDIM 1024
#define NH 16
#define HD 64
#define NKEEP 2048
#define QW 64
#define SCALE 0.125f

// Scratch (device globals; allocation is forbidden)
__device__ float g_Qh[BATCH * NH * NQ * HD];
__device__ float g_Kh[BATCH * NH * NKV * HD];
__device__ float g_Vh[BATCH * NH * NKV * HD];
__device__ float g_AO[BATCH * NQ * CDIM];
__device__ float g_ct[NQ * 32];
__device__ float g_st[NQ * 32];

// ---------------------------------------------------------------------------
__device__ __forceinline__ float f2tf(float f) {
    uint32_t u;
    asm("cvt.rna.tf32.f32 %0, %1;" : "=r"(u) : "f"(f));
    return __uint_as_float(u);
}
__device__ __forceinline__ float4 f2tf4(float4 v) {
    return make_float4(f2tf(v.x), f2tf(v.y), f2tf(v.z), f2tf(v.w));
}

__device__ __forceinline__ void mma8(float c[4], float a0, float a1, float a2, float a3,
                                     float b0, float b1) {
    asm volatile(
        "mma.sync.aligned.m16n8k8.row.col.f32.tf32.tf32.f32 "
        "{%0,%1,%2,%3}, {%4,%5,%6,%7}, {%8,%9}, {%0,%1,%2,%3};\n"
        : "+f"(c[0]), "+f"(c[1]), "+f"(c[2]), "+f"(c[3])
        : "r"(__float_as_uint(a0)), "r"(__float_as_uint(a1)),
          "r"(__float_as_uint(a2)), "r"(__float_as_uint(a3)),
          "r"(__float_as_uint(b0)), "r"(__float_as_uint(b1)));
}

// ---------------------------------------------------------------------------
__global__ void rope_table_kernel(float* __restrict__ ct, float* __restrict__ st) {
    int idx = blockIdx.x * blockDim.x + threadIdx.x;
    if (idx >= NQ * 32) return;
    int n = idx >> 5;
    int p = idx & 31;
    int j = p & 15;
    float coord = (p < 16) ? (float)(n & (QW - 1)) : (float)(n / QW);
    float freq = powf(10000.0f, -(float)j / 16.0f);
    float ang = coord * freq;
    ct[idx] = cosf(ang);
    st[idx] = sinf(ang);
}

// ---------------------------------------------------------------------------
// tf32 GEMM: out = X(M x 1024) @ W(1024 x 1024) + bias.
// Block 128x128, BK=16, 256 threads (8 warps 4x2, warp tile 32x64).
// Double-buffered smem + register prefetch; one __syncthreads per K-iter.
// Epilogue modes: 0 V-scatter, 1 Q(+RoPE), 2 K(+RoPE if n<NKEEP), 3 row-major.
// ---------------------------------------------------------------------------
#define BK 16
#define A_STR 20     // (m row stride) -> conflict-free frag loads
#define B_STR 136    // (k row stride) -> conflict-free frag loads
#define NK_IT 64     // 1024 / BK

__global__ __launch_bounds__(256, 2)
void gemm_tf32(const float* __restrict__ A, const float* __restrict__ W,
               const float* __restrict__ bias, float* __restrict__ out,
               int Ntok, int mode,
               const float* __restrict__ ct, const float* __restrict__ st) {
    __shared__ float As[2][128 * A_STR];
    __shared__ float Bs[2][BK * B_STR];

    int tid = threadIdx.x;
    int lane = tid & 31, wid = tid >> 5;
    int wm = wid >> 1, wn = wid & 1;
    int g = lane >> 2, q4 = lane & 3;
    int row0 = blockIdx.y * 128, col0 = blockIdx.x * 128;

    // staging: A 128x16 -> 8 floats/thread;  B 16x128 -> 8 floats/thread
    int ar = tid >> 1, ac = (tid & 1) << 3;
    int br = tid >> 4, bc = (tid & 15) << 3;

    const float* Ap = A + (size_t)(row0 + ar) * 1024 + ac;
    const float* Wp = W + (size_t)br * 1024 + col0 + bc;

    float acc[2][8][4];
#pragma unroll
    for (int mi = 0; mi < 2; mi++)
#pragma unroll
        for (int ni = 0; ni < 8; ni++)
#pragma unroll
            for (int j = 0; j < 4; j++) acc[mi][ni][j] = 0.0f;

    // prologue: stage tile 0
    {
        float4 a0 = *(const float4*)(Ap);
        float4 a1 = *(const float4*)(Ap + 4);
        float4 b0 = *(const float4*)(Wp);
        float4 b1 = *(const float4*)(Wp + 4);
        *(float4*)&As[0][ar * A_STR + ac]     = f2tf4(a0);
        *(float4*)&As[0][ar * A_STR + ac + 4] = f2tf4(a1);
        *(float4*)&Bs[0][br * B_STR + bc]     = f2tf4(b0);
        *(float4*)&Bs[0][br * B_STR + bc + 4] = f2tf4(b1);
    }

    int cur = 0;
    for (int it = 1; it <= NK_IT; it++) {
        __syncthreads();

        float4 na0, na1, nb0, nb1;
        if (it < NK_IT) {
            na0 = *(const float4*)(Ap + it * BK);
            na1 = *(const float4*)(Ap + it * BK + 4);
            nb0 = *(const float4*)(Wp + (size_t)it * BK * 1024);
            nb1 = *(const float4*)(Wp + (size_t)it * BK * 1024 + 4);
        }

        const float* Ac = As[cur];
        const float* Bc = Bs[cur];
#pragma unroll
        for (int kc = 0; kc < BK; kc += 8) {
            float a[2][4], b[8][2];
#pragma unroll
            for (int mi = 0; mi < 2; mi++) {
                int m = wm * 32 + mi * 16;
                a[mi][0] = Ac[(m + g) * A_STR + kc + q4];
                a[mi][1] = Ac[(m + 8 + g) * A_STR + kc + q4];
                a[mi][2] = Ac[(m + g) * A_STR + kc + 4 + q4];
                a[mi][3] = Ac[(m + 8 + g) * A_STR + kc + 4 + q4];
            }
#pragma unroll
            for (int ni = 0; ni < 8; ni++) {
                int n = wn * 64 + ni * 8 + g;
                b[ni][0] = Bc[(kc + q4) * B_STR + n];
                b[ni][1] = Bc[(kc + 4 + q4) * B_STR + n];
            }
#pragma unroll
            for (int mi = 0; mi < 2; mi++)
#pragma unroll
                for (int ni = 0; ni < 8; ni++)
                    mma8(acc[mi][ni], a[mi][0], a[mi][1], a[mi][2], a[mi][3],
                         b[ni][0], b[ni][1]);
        }

        if (it < NK_IT) {
            int nxt = cur ^ 1;
            *(float4*)&As[nxt][ar * A_STR + ac]     = f2tf4(na0);
            *(float4*)&As[nxt][ar * A_STR + ac + 4] = f2tf4(na1);
            *(float4*)&Bs[nxt][br * B_STR + bc]     = f2tf4(nb0);
            *(float4*)&Bs[nxt][br * B_STR + bc + 4] = f2tf4(nb1);
        }
        cur ^= 1;
    }

    // epilogue
#pragma unroll
    for (int mi = 0; mi < 2; mi++) {
#pragma unroll
        for (int ri = 0; ri < 2; ri++) {
            int gr = row0 + wm * 32 + mi * 16 + ri * 8 + g;
            int b = 0, n = gr;
            if (mode != 3) { b = gr / Ntok; n = gr - b * Ntok; }
            bool dorope = (mode == 1) || (mode == 2 && n < NKEEP);
#pragma unroll
            for (int ni = 0; ni < 8; ni++) {
                int gc = col0 + wn * 64 + ni * 8 + 2 * q4;
                float v0 = acc[mi][ni][ri * 2 + 0] + bias[gc];
                float v1 = acc[mi][ni][ri * 2 + 1] + bias[gc + 1];
                if (mode == 3) {
                    *(float2*)(out + (size_t)gr * 1024 + gc) = make_float2(v0, v1);
                } else {
                    if (dorope) {
                        int p = (gc & 63) >> 1;
                        float cs = ct[n * 32 + p];
                        float sn = st[n * 32 + p];
                        float e = v0, o = v1;
                        v0 = e * cs - o * sn;
                        v1 = e * sn + o * cs;
                    }
                    int h = (gc >> 6) & 15;
                    float* dst = out + (((size_t)(b * NH + h) * Ntok + n) * HD + (gc & 63));
                    *(float2*)dst = make_float2(v0, v1);
                }
            }
        }
    }
}

// ---------------------------------------------------------------------------
// tf32 flash attention: block = one (b,h), 128 q rows; 8 warps x 16 rows.
// Bc = 64; double-buffered K/V smem + register prefetch; 1 syncthreads/tile.
// ---------------------------------------------------------------------------
#define QS_S 68
#define KS_S 68
#define VS_S 72
#define PS_S 68
#define NTILE (NKV / 64)
#define FLASH_SMEM ((128 * QS_S + 2 * 64 * KS_S + 2 * 64 * VS_S + 128 * PS_S) * 4)

__global__ __launch_bounds__(256)
void flash_tf32(const float* __restrict__ Qh, const float* __restrict__ Kh,
                const float* __restrict__ Vh, float* __restrict__ Out) {
    extern __shared__ float sm[];
    float* Qs = sm;                                    // [128][68]
    float* Ks0 = Qs + 128 * QS_S;                      // [2][64][68]
    float* Vs0 = Ks0 + 2 * 64 * KS_S;                  // [2][64][72]
    float* Ps = Vs0 + 2 * 64 * VS_S;                   // [128][68]

    int tid = threadIdx.x, lane = tid & 31, wid = tid >> 5;
    int g = lane >> 2, q4 = lane & 3;
    int bh = blockIdx.y, qt = blockIdx.x;
    int r0 = wid * 16;

    const float* Qb = Qh + ((size_t)bh * NQ + qt * 128) * HD;
    const float* Kb = Kh + (size_t)bh * NKV * HD;
    const float* Vb = Vh + (size_t)bh * NKV * HD;

    // staging coords: idx = tid + t*256 -> r = idx>>4, dg = (idx&15)<<2
    int sr[4], sdg[4];
#pragma unroll
    for (int t = 0; t < 4; t++) {
        int idx = tid + t * 256;
        sr[t] = idx >> 4;
        sdg[t] = (idx & 15) << 2;
    }

    // stage Q (scaled, tf32)
#pragma unroll
    for (int t = 0; t < 8; t++) {
        int idx = tid + t * 256;
        int r = idx >> 4, dg = (idx & 15) << 2;
        float4 v = *(const float4*)(Qb + r * 64 + dg);
        float4 w = make_float4(f2tf(v.x * SCALE), f2tf(v.y * SCALE),
                               f2tf(v.z * SCALE), f2tf(v.w * SCALE));
        *(float4*)&Qs[r * QS_S + dg] = w;
    }

    // stage K/V tile 0 into buffer 0
#pragma unroll
    for (int t = 0; t < 4; t++) {
        float4 kv = *(const float4*)(Kb + sr[t] * 64 + sdg[t]);
        float4 vv = *(const float4*)(Vb + sr[t] * 64 + sdg[t]);
        *(float4*)&Ks0[sr[t] * KS_S + sdg[t]] = f2tf4(kv);
        *(float4*)&Vs0[sr[t] * VS_S + sdg[t]] = f2tf4(vv);
    }

    float m0 = -INFINITY, m1 = -INFINITY, l0 = 0.0f, l1 = 0.0f;
    float o[8][4];
#pragma unroll
    for (int ni = 0; ni < 8; ni++)
#pragma unroll
        for (int j = 0; j < 4; j++) o[ni][j] = 0.0f;

    int cur = 0;
    for (int kt = 0; kt < NTILE; kt++) {
        __syncthreads();

        // prefetch next K/V tile into registers
        float4 pk[4], pv[4];
        if (kt + 1 < NTILE) {
            const float* Kn = Kb + (size_t)(kt + 1) * 64 * 64;
            const float* Vn = Vb + (size_t)(kt + 1) * 64 * 64;
#pragma unroll
            for (int t = 0; t < 4; t++) {
                pk[t] = *(const float4*)(Kn + sr[t] * 64 + sdg[t]);
                pv[t] = *(const float4*)(Vn + sr[t] * 64 + sdg[t]);
            }
        }

        const float* Ksc = Ks0 + cur * 64 * KS_S;
        const float* Vsc = Vs0 + cur * 64 * VS_S;

        // S = Q @ K^T  (16 x 64 per warp)
        float s[8][4];
#pragma unroll
        for (int ni = 0; ni < 8; ni++)
#pragma unroll
            for (int j = 0; j < 4; j++) s[ni][j] = 0.0f;

#pragma unroll
        for (int kc = 0; kc < 64; kc += 8) {
            float a0 = Qs[(r0 + g) * QS_S + kc + q4];
            float a1 = Qs[(r0 + 8 + g) * QS_S + kc + q4];
            float a2 = Qs[(r0 + g) * QS_S + kc + 4 + q4];
            float a3 = Qs[(r0 + 8 + g) * QS_S + kc + 4 + q4];
#pragma unroll
            for (int ni = 0; ni < 8; ni++) {
                float b0 = Ksc[(ni * 8 + g) * KS_S + kc + q4];
                float b1 = Ksc[(ni * 8 + g) * KS_S + kc + 4 + q4];
                mma8(s[ni], a0, a1, a2, a3, b0, b1);
            }
        }

        // online softmax
        float mt0 = -INFINITY, mt1 = -INFINITY;
#pragma unroll
        for (int ni = 0; ni < 8; ni++) {
            mt0 = fmaxf(mt0, fmaxf(s[ni][0], s[ni][1]));
            mt1 = fmaxf(mt1, fmaxf(s[ni][2], s[ni][3]));
        }
        mt0 = fmaxf(mt0, __shfl_xor_sync(0xffffffffu, mt0, 1));
        mt0 = fmaxf(mt0, __shfl_xor_sync(0xffffffffu, mt0, 2));
        mt1 = fmaxf(mt1, __shfl_xor_sync(0xffffffffu, mt1, 1));
        mt1 = fmaxf(mt1, __shfl_xor_sync(0xffffffffu, mt1, 2));
        float mn0 = fmaxf(m0, mt0), mn1 = fmaxf(m1, mt1);
        float al0 = __expf(m0 - mn0), al1 = __expf(m1 - mn1);
        m0 = mn0; m1 = mn1;

        float sum0 = 0.0f, sum1 = 0.0f;
#pragma unroll
        for (int ni = 0; ni < 8; ni++) {
            s[ni][0] = __expf(s[ni][0] - mn0);
            s[ni][1] = __expf(s[ni][1] - mn0);
            s[ni][2] = __expf(s[ni][2] - mn1);
            s[ni][3] = __expf(s[ni][3] - mn1);
            sum0 += s[ni][0] + s[ni][1];
            sum1 += s[ni][2] + s[ni][3];
        }
        sum0 += __shfl_xor_sync(0xffffffffu, sum0, 1);
        sum0 += __shfl_xor_sync(0xffffffffu, sum0, 2);
        sum1 += __shfl_xor_sync(0xffffffffu, sum1, 1);
        sum1 += __shfl_xor_sync(0xffffffffu, sum1, 2);
        l0 = l0 * al0 + sum0;
        l1 = l1 * al1 + sum1;
#pragma unroll
        for (int ni = 0; ni < 8; ni++) {
            o[ni][0] *= al0; o[ni][1] *= al0;
            o[ni][2] *= al1; o[ni][3] *= al1;
        }

        // P (warp-private slab), tf32
#pragma unroll
        for (int ni = 0; ni < 8; ni++) {
            int c = ni * 8 + 2 * q4;
            *(float2*)&Ps[(r0 + g) * PS_S + c] =
                make_float2(f2tf(s[ni][0]), f2tf(s[ni][1]));
            *(float2*)&Ps[(r0 + 8 + g) * PS_S + c] =
                make_float2(f2tf(s[ni][2]), f2tf(s[ni][3]));
        }
        __syncwarp();

        // O += P @ V
#pragma unroll
        for (int kc = 0; kc < 64; kc += 8) {
            float a0 = Ps[(r0 + g) * PS_S + kc + q4];
            float a1 = Ps[(r0 + 8 + g) * PS_S + kc + q4];
            float a2 = Ps[(r0 + g) * PS_S + kc + 4 + q4];
            float a3 = Ps[(r0 + 8 + g) * PS_S + kc + 4 + q4];
#pragma unroll
            for (int ni = 0; ni < 8; ni++) {
                float b0 = Vsc[(kc + q4) * VS_S + ni * 8 + g];
                float b1 = Vsc[(kc + 4 + q4) * VS_S + ni * 8 + g];
                mma8(o[ni], a0, a1, a2, a3, b0, b1);
            }
        }

        // store prefetched tile into the other buffer
        if (kt + 1 < NTILE) {
            int nxt = cur ^ 1;
            float* Kn = Ks0 + nxt * 64 * KS_S;
            float* Vn = Vs0 + nxt * 64 * VS_S;
#pragma unroll
            for (int t = 0; t < 4; t++) {
                *(float4*)&Kn[sr[t] * KS_S + sdg[t]] = f2tf4(pk[t]);
                *(float4*)&Vn[sr[t] * VS_S + sdg[t]] = f2tf4(pv[t]);
            }
        }
        cur ^= 1;
    }

    // epilogue: write to (B, Nq, C) layout
    float inv0 = 1.0f / l0, inv1 = 1.0f / l1;
    int b = bh >> 4, h = bh & 15;
    int nr = qt * 128 + r0 + g;
    size_t base0 = ((size_t)(b * NQ + nr)) * CDIM + h * 64;
    size_t base1 = base0 + (size_t)8 * CDIM;
#pragma unroll
    for (int ni = 0; ni < 8; ni++) {
        int c = ni * 8 + 2 * q4;
        *(float2*)(Out + base0 + c) = make_float2(o[ni][0] * inv0, o[ni][1] * inv0);
        *(float2*)(Out + base1 + c) = make_float2(o[ni][2] * inv1, o[ni][3] * inv1);
    }
}

// ---------------------------------------------------------------------------
extern "C" void kernel_launch(void* const* d_in, const int* in_sizes, int n_in,
                              void* d_out, int out_size) {
    const float* q  = (const float*)d_in[0];
    const float* k  = (const float*)d_in[1];
    const float* v  = (const float*)d_in[2];
    const float* Wq = (const float*)d_in[3];
    const float* bq = (const float*)d_in[4];
    const float* Wk = (const float*)d_in[5];
    const float* bk = (const float*)d_in[6];
    const float* Wv = (const float*)d_in[7];
    const float* bv = (const float*)d_in[8];
    const float* Wo = (const float*)d_in[9];
    const float* bo = (const float*)d_in[10];
    float* out = (float*)d_out;

    float *pQ, *pK, *pV, *pAO, *pc, *ps;
    cudaGetSymbolAddress((void**)&pQ,  g_Qh);
    cudaGetSymbolAddress((void**)&pK,  g_Kh);
    cudaGetSymbolAddress((void**)&pV,  g_Vh);
    cudaGetSymbolAddress((void**)&pAO, g_AO);
    cudaGetSymbolAddress((void**)&pc,  g_ct);
    cudaGetSymbolAddress((void**)&ps,  g_st);

    cudaFuncSetAttribute(flash_tf32, cudaFuncAttributeMaxDynamicSharedMemorySize,
                         FLASH_SMEM);

    rope_table_kernel<<<(NQ * 32 + 255) / 256, 256>>>(pc, ps);

    gemm_tf32<<<dim3(8, (BATCH * NQ)  / 128), 256>>>(q, Wq, bq, pQ, NQ,  1, pc, ps);
    gemm_tf32<<<dim3(8, (BATCH * NKV) / 128), 256>>>(k, Wk, bk, pK, NKV, 2, pc, ps);
    gemm_tf32<<<dim3(8, (BATCH * NKV) / 128), 256>>>(v, Wv, bv, pV, NKV, 0, pc, ps);

    flash_tf32<<<dim3(NQ / 128, BATCH * NH), 256, FLASH_SMEM>>>(pQ, pK, pV, pAO);

    gemm_tf32<<<dim3(8, (BATCH * NQ) / 128), 256>>>(pAO, Wo, bo, out, NQ, 3, pc, ps);
}